// round 14
// baseline (speedup 1.0000x reference)
#include <cuda_runtime.h>
#include <cuda_fp16.h>
#include <cstdint>

// Problem constants
#define BATCH 256
#define TT    256
#define DM    384
#define DKV   64
#define BT    (BATCH*TT)

// ---------------------------------------------------------------------------
// Scratch: only W^T fp16 remains in gmem. q/k/v never leave shared memory.
// ---------------------------------------------------------------------------
__device__ __align__(16) __half g_wh[192 * DM];

// ---------------------------------------------------------------------------
// PTX helpers (sm_80-era: mma.sync + ldmatrix + cp.async, valid at compute_103)
// ---------------------------------------------------------------------------
__device__ __forceinline__ uint32_t smem_u32(const void* p) {
    uint32_t a;
    asm("{ .reg .u64 t; cvta.to.shared.u64 t, %1; cvt.u32.u64 %0, t; }"
        : "=r"(a) : "l"(p));
    return a;
}
__device__ __forceinline__ void ldsm_x4(uint32_t addr, uint32_t* r) {
    asm volatile("ldmatrix.sync.aligned.m8n8.x4.shared.b16 {%0,%1,%2,%3}, [%4];"
                 : "=r"(r[0]), "=r"(r[1]), "=r"(r[2]), "=r"(r[3]) : "r"(addr));
}
__device__ __forceinline__ void ldsm_x4t(uint32_t addr, uint32_t* r) {
    asm volatile("ldmatrix.sync.aligned.m8n8.x4.trans.shared.b16 {%0,%1,%2,%3}, [%4];"
                 : "=r"(r[0]), "=r"(r[1]), "=r"(r[2]), "=r"(r[3]) : "r"(addr));
}
__device__ __forceinline__ void mma_fp16(float* c, const uint32_t* a,
                                         uint32_t b0, uint32_t b1) {
    asm volatile(
        "mma.sync.aligned.m16n8k16.row.col.f32.f16.f16.f32 "
        "{%0,%1,%2,%3}, {%4,%5,%6,%7}, {%8,%9}, {%0,%1,%2,%3};"
        : "+f"(c[0]), "+f"(c[1]), "+f"(c[2]), "+f"(c[3])
        : "r"(a[0]), "r"(a[1]), "r"(a[2]), "r"(a[3]), "r"(b0), "r"(b1));
}
__device__ __forceinline__ float ex2(float x) {
    float y;
    asm("ex2.approx.ftz.f32 %0, %1;" : "=f"(y) : "f"(x));
    return y;
}
__device__ __forceinline__ void split2h(float x, float y, uint32_t& h, uint32_t& l) {
    __half h0 = __float2half_rn(x), h1 = __float2half_rn(y);
    __half l0 = __float2half_rn(x - __half2float(h0));
    __half l1 = __float2half_rn(y - __half2float(h1));
    __half2 hp = __halves2half2(h0, h1);
    __half2 lp = __halves2half2(l0, l1);
    h = *(uint32_t*)&hp; l = *(uint32_t*)&lp;
}
__device__ __forceinline__ uint32_t pack2h(float x, float y) {
    __half2 hp = __halves2half2(__float2half_rn(x), __float2half_rn(y));
    return *(uint32_t*)&hp;
}
#define CP_ASYNC16(dst, src) \
    asm volatile("cp.async.cg.shared.global [%0], [%1], 16;" \
                 :: "r"(dst), "l"(src) : "memory")
#define CP_COMMIT() asm volatile("cp.async.commit_group;" ::: "memory")
#define CP_WAIT(n)  asm volatile("cp.async.wait_group %0;" :: "n"(n) : "memory")

// ---------------------------------------------------------------------------
// Kernel 0: W^T fp16 conversion, coalesced reads via smem transpose.
// ---------------------------------------------------------------------------
__global__ void wconv_kernel(const float* __restrict__ Wq,
                             const float* __restrict__ Wk,
                             const float* __restrict__ Wv) {
    __shared__ float t[32][65];
    const int mat = blockIdx.x / 12;          // 0..2
    const int k0  = (blockIdx.x % 12) * 32;
    const float* W = (mat == 0) ? Wq : (mat == 1) ? Wk : Wv;
    const int tid = threadIdx.x;

    {
        const int n  = tid & 63;
        const int kl = tid >> 6;
        #pragma unroll
        for (int i = 0; i < 8; i++) {
            const int k = kl + i * 4;
            t[k][n] = W[(size_t)(k0 + k) * DKV + n];
        }
    }
    __syncthreads();
    {
        const int kl = tid & 31;
        const int nl = tid >> 5;
        #pragma unroll
        for (int i = 0; i < 8; i++) {
            const int n = nl + i * 8;
            g_wh[(size_t)(mat * 64 + n) * DM + k0 + kl] = __float2half_rn(t[kl][n]);
        }
    }
}

// ---------------------------------------------------------------------------
// FUSED kernel: per-batch QKV projection (2 x proj pipeline, epilogue to smem)
// followed by causal attention with per-warp tile pairing (w, 15-w) so every
// warp does exactly 9 key-rounds (perfect balance).
// ---------------------------------------------------------------------------
#define BM   128
#define BKS  32
#define NKS  (DM / BKS)
#define PAD  40
#define APAD 72

#define A_SZ (BM * PAD)          // 5120
#define B_SZ (192 * PAD)         // 7680
#define OFF_A(buf)  ((buf) * A_SZ)
#define OFF_B(buf)  (3 * A_SZ + (buf) * B_SZ)
#define OFF_QH      (3 * A_SZ + 3 * B_SZ)          // 38400
#define OFF_QL      (OFF_QH + TT * APAD)
#define OFF_KH      (OFF_QL + TT * APAD)
#define OFF_VH      (OFF_KH + TT * APAD)
#define SM_TOT      (OFF_VH + TT * APAD)           // 112128 fp16 = 224256 B

__global__ void __launch_bounds__(256, 1) fused_kernel(const float* __restrict__ X,
                                                       float* __restrict__ out) {
    extern __shared__ __half sm[];
    const uint32_t sb = smem_u32(sm);

    const int b    = blockIdx.x;
    const int tid  = threadIdx.x;
    const int lane = tid & 31;
    const int wid  = tid >> 5;
    const int warp_m = wid & 3;
    const int warp_n = wid >> 2;

    // =====================  PHASE 1: projection (2 halves)  =================
    for (int hf = 0; hf < 2; hf++) {
        const int row0 = b * TT + hf * BM;

        float acc[2][12][4];
        #pragma unroll
        for (int m = 0; m < 2; m++)
            #pragma unroll
            for (int n = 0; n < 12; n++)
                #pragma unroll
                for (int j = 0; j < 4; j++) acc[m][n][j] = 0.f;

        float4 xa[4];
        const int br  = tid >> 2;
        const int bc8 = tid & 3;

        auto cp_b = [&](int ks, int buf) {
            const int k0 = ks * BKS;
            #pragma unroll
            for (int i = 0; i < 3; i++) {
                int r = br + i * 64;
                uint32_t dst = sb + (uint32_t)(OFF_B(buf) + r * PAD + bc8 * 8) * 2;
                CP_ASYNC16(dst, g_wh + r * DM + k0 + bc8 * 8);
            }
        };
        auto load_x = [&](int ks) {
            const int k0 = ks * BKS;
            #pragma unroll
            for (int i = 0; i < 4; i++) {
                int f  = tid + i * 256;
                int r  = f >> 3;
                int c4 = f & 7;
                xa[i] = *(const float4*)(X + (size_t)(row0 + r) * DM + k0 + c4 * 4);
            }
        };
        auto store_x = [&](int buf) {
            #pragma unroll
            for (int i = 0; i < 4; i++) {
                int f  = tid + i * 256;
                int r  = f >> 3;
                int c4 = f & 7;
                float4 v = xa[i];
                *(uint2*)(sm + OFF_A(buf) + r * PAD + c4 * 4) =
                    make_uint2(pack2h(v.x, v.y), pack2h(v.z, v.w));
            }
        };

        cp_b(0, 0); CP_COMMIT();
        cp_b(1, 1); CP_COMMIT();
        load_x(0);
        store_x(0);
        CP_WAIT(1);
        __syncthreads();

        for (int ks = 0; ks < NKS; ks++) {
            if (ks + 2 < NKS) { cp_b(ks + 2, (ks + 2) % 3); CP_COMMIT(); }
            if (ks + 1 < NKS) load_x(ks + 1);

            const uint32_t a_base = sb + OFF_A(ks % 3) * 2;
            const uint32_t b_base = sb + OFF_B(ks % 3) * 2;

            #pragma unroll
            for (int kk = 0; kk < 2; kk++) {
                uint32_t ah[2][4];
                const int arow_l = (lane & 15);
                const int acol   = kk * 16 + ((lane >> 4) << 3);
                #pragma unroll
                for (int mt = 0; mt < 2; mt++) {
                    const int arow = warp_m * 32 + mt * 16 + arow_l;
                    ldsm_x4(a_base + (uint32_t)(arow * PAD + acol) * 2, ah[mt]);
                }
                const int brow_l = (lane & 7) + ((lane & 16) >> 1);
                const int bcol   = kk * 16 + (lane & 8);
                #pragma unroll
                for (int g2 = 0; g2 < 6; g2++) {
                    uint32_t bh[4];
                    const int brow = warp_n * 96 + g2 * 16 + brow_l;
                    ldsm_x4(b_base + (uint32_t)(brow * PAD + bcol) * 2, bh);
                    #pragma unroll
                    for (int mt = 0; mt < 2; mt++) {
                        #pragma unroll
                        for (int h = 0; h < 2; h++) {
                            mma_fp16(acc[mt][g2 * 2 + h], ah[mt],
                                     bh[h * 2], bh[h * 2 + 1]);
                        }
                    }
                }
            }

            if (ks + 1 < NKS) {
                store_x((ks + 1) % 3);
                if (ks + 2 < NKS) { CP_WAIT(1); }
                else              { CP_WAIT(0); }
                __syncthreads();
            }
        }

        // ---- epilogue: q -> smem hi/lo fp16, k/v -> smem fp16 ----
        const int gi = lane >> 2;
        const int ti = lane & 3;
        #pragma unroll
        for (int mt = 0; mt < 2; mt++) {
            const int lrow = hf * BM + warp_m * 32 + mt * 16 + gi;
            #pragma unroll
            for (int nt = 0; nt < 12; nt++) {
                const int col = warp_n * 96 + nt * 8 + ti * 2;
                if (col < 64) {
                    uint32_t h0, l0, h1, l1;
                    split2h(acc[mt][nt][0], acc[mt][nt][1], h0, l0);
                    split2h(acc[mt][nt][2], acc[mt][nt][3], h1, l1);
                    *(uint32_t*)(sm + OFF_QH + lrow * APAD + col) = h0;
                    *(uint32_t*)(sm + OFF_QL + lrow * APAD + col) = l0;
                    *(uint32_t*)(sm + OFF_QH + (lrow + 8) * APAD + col) = h1;
                    *(uint32_t*)(sm + OFF_QL + (lrow + 8) * APAD + col) = l1;
                } else {
                    const int o = (col < 128) ? OFF_KH : OFF_VH;
                    const int c = col & 63;
                    *(uint32_t*)(sm + o + lrow * APAD + c) =
                        pack2h(acc[mt][nt][0], acc[mt][nt][1]);
                    *(uint32_t*)(sm + o + (lrow + 8) * APAD + c) =
                        pack2h(acc[mt][nt][2], acc[mt][nt][3]);
                }
            }
        }
        __syncthreads();
    }

    // =====================  PHASE 2: causal attention  ======================
    // Warp handles m16 tiles (wid) and (15-wid): exactly 9 rounds per warp.
    const int g  = lane >> 2;
    const int tg = lane & 3;
    const float SC = 0.125f * 1.44269504f;

    const int krow = (lane & 7) + ((lane & 16) >> 1);
    const int koff = (lane & 8);
    const int vkey = lane & 15;
    const int voff = (lane >> 4) << 3;

    float* ob = out + ((size_t)b * TT) * DKV;

    #pragma unroll
    for (int mtile = 0; mtile < 2; mtile++) {
        const int t  = mtile ? (15 - wid) : wid;
        const int R0 = t * 16;

        // Q fragments for this tile
        uint32_t qh[4][4], ql[4][4];
        #pragma unroll
        for (int kk = 0; kk < 4; kk++) {
            const int arow = R0 + (lane & 15);
            const int acol = kk * 16 + ((lane >> 4) << 3);
            ldsm_x4(sb + (uint32_t)(OFF_QH + arow * APAD + acol) * 2, qh[kk]);
            ldsm_x4(sb + (uint32_t)(OFF_QL + arow * APAD + acol) * 2, ql[kk]);
        }

        float m2[2] = {-1e30f, -1e30f};
        float l2[2] = {0.f, 0.f};
        float O[8][4];
        #pragma unroll
        for (int n = 0; n < 8; n++)
            #pragma unroll
            for (int j = 0; j < 4; j++) O[n][j] = 0.f;

        const int nr = (t + 2) >> 1;           // ceil((t+1)/2) rounds of 32 keys
        for (int kr = 0; kr < nr; kr++) {
            const int j0   = kr * 32;
            const bool last = (kr == nr - 1);
            const bool full = !(last && ((t & 1) == 0));  // upper 16 keys live?

            float S[4][4];
            #pragma unroll
            for (int nt = 0; nt < 4; nt++)
                #pragma unroll
                for (int j = 0; j < 4; j++) S[nt][j] = 0.f;

            const uint32_t kb0 = sb + (uint32_t)(OFF_KH + (j0 + krow) * APAD + koff) * 2;
            const uint32_t kb1 = kb0 + (uint32_t)(16 * APAD) * 2;
            #pragma unroll
            for (int kk = 0; kk < 4; kk++) {
                uint32_t b0[4];
                ldsm_x4(kb0 + kk * 32, b0);
                mma_fp16(S[0], qh[kk], b0[0], b0[1]);
                mma_fp16(S[1], qh[kk], b0[2], b0[3]);
                mma_fp16(S[0], ql[kk], b0[0], b0[1]);
                mma_fp16(S[1], ql[kk], b0[2], b0[3]);
                if (full) {
                    uint32_t b1[4];
                    ldsm_x4(kb1 + kk * 32, b1);
                    mma_fp16(S[2], qh[kk], b1[0], b1[1]);
                    mma_fp16(S[3], qh[kk], b1[2], b1[3]);
                    mma_fp16(S[2], ql[kk], b1[0], b1[1]);
                    mma_fp16(S[3], ql[kk], b1[2], b1[3]);
                }
            }

            if (last) {
                #pragma unroll
                for (int nt = 0; nt < 4; nt++)
                    #pragma unroll
                    for (int j = 0; j < 4; j++) {
                        const int row = R0 + g + ((j >> 1) << 3);
                        const int col = j0 + nt * 8 + tg * 2 + (j & 1);
                        if (col > row) S[nt][j] = -3e38f;
                    }
            }

            uint32_t pa0[4], pa1[4];
            #pragma unroll
            for (int h = 0; h < 2; h++) {
                float v0 = S[0][h * 2] * SC, v1 = S[0][h * 2 + 1] * SC;
                float v2 = S[1][h * 2] * SC, v3 = S[1][h * 2 + 1] * SC;
                float mx = fmaxf(fmaxf(v0, v1), fmaxf(v2, v3));
                float v4, v5, v6, v7;
                if (full) {
                    v4 = S[2][h * 2] * SC; v5 = S[2][h * 2 + 1] * SC;
                    v6 = S[3][h * 2] * SC; v7 = S[3][h * 2 + 1] * SC;
                    mx = fmaxf(mx, fmaxf(fmaxf(v4, v5), fmaxf(v6, v7)));
                }
                mx = fmaxf(mx, __shfl_xor_sync(0xFFFFFFFFu, mx, 1));
                mx = fmaxf(mx, __shfl_xor_sync(0xFFFFFFFFu, mx, 2));
                const float mnew = fmaxf(m2[h], mx);
                const float sc   = ex2(m2[h] - mnew);
                m2[h] = mnew;
                const float p0 = ex2(v0 - mnew), p1 = ex2(v1 - mnew);
                const float p2 = ex2(v2 - mnew), p3 = ex2(v3 - mnew);
                float psum = (p0 + p1) + (p2 + p3);
                if (full) {
                    const float p4 = ex2(v4 - mnew), p5 = ex2(v5 - mnew);
                    const float p6 = ex2(v6 - mnew), p7 = ex2(v7 - mnew);
                    psum += (p4 + p5) + (p6 + p7);
                    pa1[h]     = pack2h(p4, p5);
                    pa1[2 + h] = pack2h(p6, p7);
                }
                l2[h] = l2[h] * sc + psum;
                #pragma unroll
                for (int n = 0; n < 8; n++) {
                    O[n][h * 2]     *= sc;
                    O[n][h * 2 + 1] *= sc;
                }
                pa0[h]     = pack2h(p0, p1);
                pa0[2 + h] = pack2h(p2, p3);
            }

            const uint32_t vb0 = sb + (uint32_t)(OFF_VH + (j0 + vkey) * APAD + voff) * 2;
            const uint32_t vb1 = vb0 + (uint32_t)(16 * APAD) * 2;
            #pragma unroll
            for (int nc = 0; nc < 4; nc++) {
                uint32_t v0[4];
                ldsm_x4t(vb0 + nc * 32, v0);
                mma_fp16(O[nc * 2],     pa0, v0[0], v0[1]);
                mma_fp16(O[nc * 2 + 1], pa0, v0[2], v0[3]);
                if (full) {
                    uint32_t v1[4];
                    ldsm_x4t(vb1 + nc * 32, v1);
                    mma_fp16(O[nc * 2],     pa1, v1[0], v1[1]);
                    mma_fp16(O[nc * 2 + 1], pa1, v1[2], v1[3]);
                }
            }
        }

        // ---- tile epilogue: quad-reduce l, normalize, store ----
        #pragma unroll
        for (int h = 0; h < 2; h++) {
            float ls = l2[h];
            ls += __shfl_xor_sync(0xFFFFFFFFu, ls, 1);
            ls += __shfl_xor_sync(0xFFFFFFFFu, ls, 2);
            const float iv = 1.f / ls;
            const int row = R0 + g + h * 8;
            #pragma unroll
            for (int n = 0; n < 8; n++) {
                *(float2*)(ob + (size_t)row * DKV + n * 8 + tg * 2) =
                    make_float2(O[n][h * 2] * iv, O[n][h * 2 + 1] * iv);
            }
        }
    }
}

// ---------------------------------------------------------------------------
// kernel_launch — graph-capturable, allocation-free
// ---------------------------------------------------------------------------
extern "C" void kernel_launch(void* const* d_in, const int* in_sizes, int n_in,
                              void* d_out, int out_size) {
    const float* x  = (const float*)d_in[0];
    const float* Wq = (const float*)d_in[1];
    const float* Wk = (const float*)d_in[2];
    const float* Wv = (const float*)d_in[3];
    float* out = (float*)d_out;
    (void)in_sizes; (void)n_in; (void)out_size;

    wconv_kernel<<<36, 256>>>(Wq, Wk, Wv);

    const int fused_smem = SM_TOT * (int)sizeof(__half);   // 224256 B
    cudaFuncSetAttribute(fused_kernel,
                         cudaFuncAttributeMaxDynamicSharedMemorySize, fused_smem);
    fused_kernel<<<BATCH, 256, fused_smem>>>(x, out);
}

// round 15
// speedup vs baseline: 1.0039x; 1.0039x over previous
#include <cuda_runtime.h>
#include <cuda_fp16.h>
#include <cstdint>

// Problem constants
#define BATCH 256
#define TT    256
#define DM    384
#define DKV   64
#define BT    (BATCH*TT)

// ---------------------------------------------------------------------------
// Scratch: only W^T fp16 remains in gmem. q/k/v never leave shared memory.
// ---------------------------------------------------------------------------
__device__ __align__(16) __half g_wh[192 * DM];

// ---------------------------------------------------------------------------
// PTX helpers (sm_80-era: mma.sync + ldmatrix + cp.async, valid at compute_103)
// ---------------------------------------------------------------------------
__device__ __forceinline__ uint32_t smem_u32(const void* p) {
    uint32_t a;
    asm("{ .reg .u64 t; cvta.to.shared.u64 t, %1; cvt.u32.u64 %0, t; }"
        : "=r"(a) : "l"(p));
    return a;
}
__device__ __forceinline__ void ldsm_x4(uint32_t addr, uint32_t* r) {
    asm volatile("ldmatrix.sync.aligned.m8n8.x4.shared.b16 {%0,%1,%2,%3}, [%4];"
                 : "=r"(r[0]), "=r"(r[1]), "=r"(r[2]), "=r"(r[3]) : "r"(addr));
}
__device__ __forceinline__ void ldsm_x4t(uint32_t addr, uint32_t* r) {
    asm volatile("ldmatrix.sync.aligned.m8n8.x4.trans.shared.b16 {%0,%1,%2,%3}, [%4];"
                 : "=r"(r[0]), "=r"(r[1]), "=r"(r[2]), "=r"(r[3]) : "r"(addr));
}
__device__ __forceinline__ void mma_fp16(float* c, const uint32_t* a,
                                         uint32_t b0, uint32_t b1) {
    asm volatile(
        "mma.sync.aligned.m16n8k16.row.col.f32.f16.f16.f32 "
        "{%0,%1,%2,%3}, {%4,%5,%6,%7}, {%8,%9}, {%0,%1,%2,%3};"
        : "+f"(c[0]), "+f"(c[1]), "+f"(c[2]), "+f"(c[3])
        : "r"(a[0]), "r"(a[1]), "r"(a[2]), "r"(a[3]), "r"(b0), "r"(b1));
}
__device__ __forceinline__ float ex2(float x) {
    float y;
    asm("ex2.approx.ftz.f32 %0, %1;" : "=f"(y) : "f"(x));
    return y;
}
__device__ __forceinline__ void split2h(float x, float y, uint32_t& h, uint32_t& l) {
    __half h0 = __float2half_rn(x), h1 = __float2half_rn(y);
    __half l0 = __float2half_rn(x - __half2float(h0));
    __half l1 = __float2half_rn(y - __half2float(h1));
    __half2 hp = __halves2half2(h0, h1);
    __half2 lp = __halves2half2(l0, l1);
    h = *(uint32_t*)&hp; l = *(uint32_t*)&lp;
}
__device__ __forceinline__ uint32_t pack2h(float x, float y) {
    __half2 hp = __halves2half2(__float2half_rn(x), __float2half_rn(y));
    return *(uint32_t*)&hp;
}
#define CP_ASYNC16(dst, src) \
    asm volatile("cp.async.cg.shared.global [%0], [%1], 16;" \
                 :: "r"(dst), "l"(src) : "memory")
#define CP_COMMIT() asm volatile("cp.async.commit_group;" ::: "memory")
#define CP_WAIT(n)  asm volatile("cp.async.wait_group %0;" :: "n"(n) : "memory")

// ---------------------------------------------------------------------------
// Kernel 0: W^T fp16 conversion, coalesced reads via smem transpose.
// ---------------------------------------------------------------------------
__global__ void wconv_kernel(const float* __restrict__ Wq,
                             const float* __restrict__ Wk,
                             const float* __restrict__ Wv) {
    __shared__ float t[32][65];
    const int mat = blockIdx.x / 12;          // 0..2
    const int k0  = (blockIdx.x % 12) * 32;
    const float* W = (mat == 0) ? Wq : (mat == 1) ? Wk : Wv;
    const int tid = threadIdx.x;

    {
        const int n  = tid & 63;
        const int kl = tid >> 6;
        #pragma unroll
        for (int i = 0; i < 8; i++) {
            const int k = kl + i * 4;
            t[k][n] = W[(size_t)(k0 + k) * DKV + n];
        }
    }
    __syncthreads();
    {
        const int kl = tid & 31;
        const int nl = tid >> 5;
        #pragma unroll
        for (int i = 0; i < 8; i++) {
            const int n = nl + i * 8;
            g_wh[(size_t)(mat * 64 + n) * DM + k0 + kl] = __float2half_rn(t[kl][n]);
        }
    }
}

// ---------------------------------------------------------------------------
// FUSED kernel: per-batch QKV projection (2 x proj pipeline, epilogue to smem)
// followed directly by R13-style causal attention (32 queries/warp, 2 m-tiles
// jointly per round) with latency cuts: V prefetch, last-round QK skip,
// first-round peel, scale folded into q.
// ---------------------------------------------------------------------------
#define BM   128
#define BKS  32
#define NKS  (DM / BKS)
#define PAD  40
#define APAD 72

#define A_SZ (BM * PAD)          // 5120
#define B_SZ (192 * PAD)         // 7680
#define OFF_A(buf)  ((buf) * A_SZ)
#define OFF_B(buf)  (3 * A_SZ + (buf) * B_SZ)
#define OFF_QH      (3 * A_SZ + 3 * B_SZ)          // 38400
#define OFF_QL      (OFF_QH + TT * APAD)
#define OFF_KH      (OFF_QL + TT * APAD)
#define OFF_VH      (OFF_KH + TT * APAD)
#define SM_TOT      (OFF_VH + TT * APAD)           // 112128 fp16 = 224256 B

__global__ void __launch_bounds__(256, 1) fused_kernel(const float* __restrict__ X,
                                                       float* __restrict__ out) {
    extern __shared__ __half sm[];
    const uint32_t sb = smem_u32(sm);

    const int b    = blockIdx.x;
    const int tid  = threadIdx.x;
    const int lane = tid & 31;
    const int wid  = tid >> 5;
    const int warp_m = wid & 3;
    const int warp_n = wid >> 2;
    const float SCQ = 0.125f * 1.44269504f;   // folded into q at epilogue

    // =====================  PHASE 1: projection (2 halves)  =================
    for (int hf = 0; hf < 2; hf++) {
        const int row0 = b * TT + hf * BM;

        float acc[2][12][4];
        #pragma unroll
        for (int m = 0; m < 2; m++)
            #pragma unroll
            for (int n = 0; n < 12; n++)
                #pragma unroll
                for (int j = 0; j < 4; j++) acc[m][n][j] = 0.f;

        float4 xa[4];
        const int br  = tid >> 2;
        const int bc8 = tid & 3;

        auto cp_b = [&](int ks, int buf) {
            const int k0 = ks * BKS;
            #pragma unroll
            for (int i = 0; i < 3; i++) {
                int r = br + i * 64;
                uint32_t dst = sb + (uint32_t)(OFF_B(buf) + r * PAD + bc8 * 8) * 2;
                CP_ASYNC16(dst, g_wh + r * DM + k0 + bc8 * 8);
            }
        };
        auto load_x = [&](int ks) {
            const int k0 = ks * BKS;
            #pragma unroll
            for (int i = 0; i < 4; i++) {
                int f  = tid + i * 256;
                int r  = f >> 3;
                int c4 = f & 7;
                xa[i] = *(const float4*)(X + (size_t)(row0 + r) * DM + k0 + c4 * 4);
            }
        };
        auto store_x = [&](int buf) {
            #pragma unroll
            for (int i = 0; i < 4; i++) {
                int f  = tid + i * 256;
                int r  = f >> 3;
                int c4 = f & 7;
                float4 v = xa[i];
                *(uint2*)(sm + OFF_A(buf) + r * PAD + c4 * 4) =
                    make_uint2(pack2h(v.x, v.y), pack2h(v.z, v.w));
            }
        };

        cp_b(0, 0); CP_COMMIT();
        cp_b(1, 1); CP_COMMIT();
        load_x(0);
        store_x(0);
        CP_WAIT(1);
        __syncthreads();

        for (int ks = 0; ks < NKS; ks++) {
            if (ks + 2 < NKS) { cp_b(ks + 2, (ks + 2) % 3); CP_COMMIT(); }
            if (ks + 1 < NKS) load_x(ks + 1);

            const uint32_t a_base = sb + OFF_A(ks % 3) * 2;
            const uint32_t b_base = sb + OFF_B(ks % 3) * 2;

            #pragma unroll
            for (int kk = 0; kk < 2; kk++) {
                uint32_t ah[2][4];
                const int arow_l = (lane & 15);
                const int acol   = kk * 16 + ((lane >> 4) << 3);
                #pragma unroll
                for (int mt = 0; mt < 2; mt++) {
                    const int arow = warp_m * 32 + mt * 16 + arow_l;
                    ldsm_x4(a_base + (uint32_t)(arow * PAD + acol) * 2, ah[mt]);
                }
                const int brow_l = (lane & 7) + ((lane & 16) >> 1);
                const int bcol   = kk * 16 + (lane & 8);
                #pragma unroll
                for (int g2 = 0; g2 < 6; g2++) {
                    uint32_t bh[4];
                    const int brow = warp_n * 96 + g2 * 16 + brow_l;
                    ldsm_x4(b_base + (uint32_t)(brow * PAD + bcol) * 2, bh);
                    #pragma unroll
                    for (int mt = 0; mt < 2; mt++) {
                        #pragma unroll
                        for (int h = 0; h < 2; h++) {
                            mma_fp16(acc[mt][g2 * 2 + h], ah[mt],
                                     bh[h * 2], bh[h * 2 + 1]);
                        }
                    }
                }
            }

            if (ks + 1 < NKS) {
                store_x((ks + 1) % 3);
                if (ks + 2 < NKS) { CP_WAIT(1); }
                else              { CP_WAIT(0); }
                __syncthreads();
            }
        }

        // ---- epilogue: q (pre-scaled) -> smem hi/lo fp16, k/v -> smem fp16 ----
        const int gi = lane >> 2;
        const int ti = lane & 3;
        #pragma unroll
        for (int mt = 0; mt < 2; mt++) {
            const int lrow = hf * BM + warp_m * 32 + mt * 16 + gi;
            #pragma unroll
            for (int nt = 0; nt < 12; nt++) {
                const int col = warp_n * 96 + nt * 8 + ti * 2;
                if (col < 64) {
                    uint32_t h0, l0, h1, l1;
                    split2h(acc[mt][nt][0] * SCQ, acc[mt][nt][1] * SCQ, h0, l0);
                    split2h(acc[mt][nt][2] * SCQ, acc[mt][nt][3] * SCQ, h1, l1);
                    *(uint32_t*)(sm + OFF_QH + lrow * APAD + col) = h0;
                    *(uint32_t*)(sm + OFF_QL + lrow * APAD + col) = l0;
                    *(uint32_t*)(sm + OFF_QH + (lrow + 8) * APAD + col) = h1;
                    *(uint32_t*)(sm + OFF_QL + (lrow + 8) * APAD + col) = l1;
                } else {
                    const int o = (col < 128) ? OFF_KH : OFF_VH;
                    const int c = col & 63;
                    *(uint32_t*)(sm + o + lrow * APAD + c) =
                        pack2h(acc[mt][nt][0], acc[mt][nt][1]);
                    *(uint32_t*)(sm + o + (lrow + 8) * APAD + c) =
                        pack2h(acc[mt][nt][2], acc[mt][nt][3]);
                }
            }
        }
        __syncthreads();
    }

    // =====================  PHASE 2: causal attention  ======================
    const int qb = (wid < 4) ? wid : (11 - wid);   // SMSP balance: pairs sum 9
    const int Q0 = qb * 32;
    const int g  = lane >> 2;
    const int tg = lane & 3;

    // Q fragments from smem (hi/lo), already scaled by 0.125*log2(e)
    uint32_t qh[2][4][4], ql[2][4][4];
    #pragma unroll
    for (int mt = 0; mt < 2; mt++) {
        #pragma unroll
        for (int kk = 0; kk < 4; kk++) {
            const int arow = Q0 + mt * 16 + (lane & 15);
            const int acol = kk * 16 + ((lane >> 4) << 3);
            ldsm_x4(sb + (uint32_t)(OFF_QH + arow * APAD + acol) * 2, qh[mt][kk]);
            ldsm_x4(sb + (uint32_t)(OFF_QL + arow * APAD + acol) * 2, ql[mt][kk]);
        }
    }

    float m[4] = {-1e30f, -1e30f, -1e30f, -1e30f};
    float lsum[4] = {0.f, 0.f, 0.f, 0.f};
    float O[2][8][4];
    #pragma unroll
    for (int mt = 0; mt < 2; mt++)
        #pragma unroll
        for (int n = 0; n < 8; n++)
            #pragma unroll
            for (int j = 0; j < 4; j++) O[mt][n][j] = 0.f;

    const int krow = (lane & 7) + ((lane & 16) >> 1);
    const int koff = (lane & 8);
    const int vkey = lane & 15;
    const int voff = (lane >> 4) << 3;

    const int nrounds = qb + 1;
    for (int kr = 0; kr < nrounds; kr++) {
        const int j0 = kr * 32;
        const bool msk = (kr == qb);    // last round (warp-uniform)

        float S[2][4][4];
        #pragma unroll
        for (int mt = 0; mt < 2; mt++)
            #pragma unroll
            for (int nt = 0; nt < 4; nt++)
                #pragma unroll
                for (int j = 0; j < 4; j++) S[mt][nt][j] = 0.f;

        const uint32_t kb0 = sb + (uint32_t)(OFF_KH + (j0 + krow) * APAD + koff) * 2;
        const uint32_t kb1 = kb0 + (uint32_t)(16 * APAD) * 2;
        #pragma unroll
        for (int kk = 0; kk < 4; kk++) {
            uint32_t b0[4], b1[4];
            ldsm_x4(kb0 + kk * 32, b0);
            ldsm_x4(kb1 + kk * 32, b1);
            // mt=0 tile
            mma_fp16(S[0][0], qh[0][kk], b0[0], b0[1]);
            mma_fp16(S[0][1], qh[0][kk], b0[2], b0[3]);
            mma_fp16(S[0][0], ql[0][kk], b0[0], b0[1]);
            mma_fp16(S[0][1], ql[0][kk], b0[2], b0[3]);
            if (!msk) {   // last round: mt0 x upper-16 keys fully masked -> skip
                mma_fp16(S[0][2], qh[0][kk], b1[0], b1[1]);
                mma_fp16(S[0][3], qh[0][kk], b1[2], b1[3]);
                mma_fp16(S[0][2], ql[0][kk], b1[0], b1[1]);
                mma_fp16(S[0][3], ql[0][kk], b1[2], b1[3]);
            }
            // mt=1 tile
            mma_fp16(S[1][0], qh[1][kk], b0[0], b0[1]);
            mma_fp16(S[1][1], qh[1][kk], b0[2], b0[3]);
            mma_fp16(S[1][0], ql[1][kk], b0[0], b0[1]);
            mma_fp16(S[1][1], ql[1][kk], b0[2], b0[3]);
            mma_fp16(S[1][2], qh[1][kk], b1[0], b1[1]);
            mma_fp16(S[1][3], qh[1][kk], b1[2], b1[3]);
            mma_fp16(S[1][2], ql[1][kk], b1[0], b1[1]);
            mma_fp16(S[1][3], ql[1][kk], b1[2], b1[3]);
        }

        // V address bases + prefetch nc=0 fragments (independent of softmax)
        const uint32_t vb0 = sb + (uint32_t)(OFF_VH + (j0 + vkey) * APAD + voff) * 2;
        const uint32_t vb1 = vb0 + (uint32_t)(16 * APAD) * 2;
        uint32_t vA[8], vB[8];
        ldsm_x4t(vb0, vA);
        ldsm_x4t(vb1, vA + 4);

        if (msk) {
            #pragma unroll
            for (int mt = 0; mt < 2; mt++)
                #pragma unroll
                for (int nt = 0; nt < 4; nt++)
                    #pragma unroll
                    for (int j = 0; j < 4; j++) {
                        const int row = Q0 + mt * 16 + g + ((j >> 1) << 3);
                        const int col = j0 + nt * 8 + tg * 2 + (j & 1);
                        if (col > row) S[mt][nt][j] = -3e38f;
                    }
        }

        uint32_t pa0[2][4], pa1[2][4];
        #pragma unroll
        for (int mt = 0; mt < 2; mt++) {
            #pragma unroll
            for (int h = 0; h < 2; h++) {
                const int rg = mt * 2 + h;
                float v0 = S[mt][0][h * 2], v1 = S[mt][0][h * 2 + 1];
                float v2 = S[mt][1][h * 2], v3 = S[mt][1][h * 2 + 1];
                float v4 = S[mt][2][h * 2], v5 = S[mt][2][h * 2 + 1];
                float v6 = S[mt][3][h * 2], v7 = S[mt][3][h * 2 + 1];
                float mx = fmaxf(fmaxf(fmaxf(v0, v1), fmaxf(v2, v3)),
                                 fmaxf(fmaxf(v4, v5), fmaxf(v6, v7)));
                mx = fmaxf(mx, __shfl_xor_sync(0xFFFFFFFFu, mx, 1));
                mx = fmaxf(mx, __shfl_xor_sync(0xFFFFFFFFu, mx, 2));
                const float mnew = fmaxf(m[rg], mx);
                const float sc   = ex2(m[rg] - mnew);
                m[rg] = mnew;
                const float p0 = ex2(v0 - mnew), p1 = ex2(v1 - mnew);
                const float p2 = ex2(v2 - mnew), p3 = ex2(v3 - mnew);
                const float p4 = ex2(v4 - mnew), p5 = ex2(v5 - mnew);
                const float p6 = ex2(v6 - mnew), p7 = ex2(v7 - mnew);
                const float psum = ((p0 + p1) + (p2 + p3)) + ((p4 + p5) + (p6 + p7));
                if (kr > 0) {
                    lsum[rg] = lsum[rg] * sc + psum;
                    #pragma unroll
                    for (int n = 0; n < 8; n++) {
                        O[mt][n][h * 2]     *= sc;
                        O[mt][n][h * 2 + 1] *= sc;
                    }
                } else {
                    lsum[rg] = psum;
                }
                pa0[mt][h]     = pack2h(p0, p1);
                pa0[mt][2 + h] = pack2h(p2, p3);
                pa1[mt][h]     = pack2h(p4, p5);
                pa1[mt][2 + h] = pack2h(p6, p7);
            }
        }

        // ---- O += P V with ping-pong V prefetch ----
        #pragma unroll
        for (int nc = 0; nc < 4; nc++) {
            uint32_t* cv = (nc & 1) ? vB : vA;
            if (nc < 3) {
                uint32_t* nv = (nc & 1) ? vA : vB;
                ldsm_x4t(vb0 + (nc + 1) * 32, nv);
                ldsm_x4t(vb1 + (nc + 1) * 32, nv + 4);
            }
            #pragma unroll
            for (int mt = 0; mt < 2; mt++) {
                mma_fp16(O[mt][nc * 2],     pa0[mt], cv[0], cv[1]);
                mma_fp16(O[mt][nc * 2 + 1], pa0[mt], cv[2], cv[3]);
                mma_fp16(O[mt][nc * 2],     pa1[mt], cv[4], cv[5]);
                mma_fp16(O[mt][nc * 2 + 1], pa1[mt], cv[6], cv[7]);
            }
        }
    }

    // ---- epilogue: quad-reduce l, normalize, store ----
    float inv[4];
    #pragma unroll
    for (int rg = 0; rg < 4; rg++) {
        float ls = lsum[rg];
        ls += __shfl_xor_sync(0xFFFFFFFFu, ls, 1);
        ls += __shfl_xor_sync(0xFFFFFFFFu, ls, 2);
        inv[rg] = 1.f / ls;
    }
    float* ob = out + ((size_t)b * TT) * DKV;
    #pragma unroll
    for (int mt = 0; mt < 2; mt++) {
        #pragma unroll
        for (int h = 0; h < 2; h++) {
            const int row = Q0 + mt * 16 + g + h * 8;
            const float iv = inv[mt * 2 + h];
            #pragma unroll
            for (int n = 0; n < 8; n++) {
                *(float2*)(ob + (size_t)row * DKV + n * 8 + tg * 2) =
                    make_float2(O[mt][n][h * 2] * iv, O[mt][n][h * 2 + 1] * iv);
            }
        }
    }
}

// ---------------------------------------------------------------------------
// kernel_launch — graph-capturable, allocation-free
// ---------------------------------------------------------------------------
extern "C" void kernel_launch(void* const* d_in, const int* in_sizes, int n_in,
                              void* d_out, int out_size) {
    const float* x  = (const float*)d_in[0];
    const float* Wq = (const float*)d_in[1];
    const float* Wk = (const float*)d_in[2];
    const float* Wv = (const float*)d_in[3];
    float* out = (float*)d_out;
    (void)in_sizes; (void)n_in; (void)out_size;

    wconv_kernel<<<36, 256>>>(Wq, Wk, Wv);

    const int fused_smem = SM_TOT * (int)sizeof(__half);   // 224256 B
    cudaFuncSetAttribute(fused_kernel,
                         cudaFuncAttributeMaxDynamicSharedMemorySize, fused_smem);
    fused_kernel<<<BATCH, 256, fused_smem>>>(x, out);
}

// round 16
// speedup vs baseline: 1.0566x; 1.0525x over previous
#include <cuda_runtime.h>
#include <cuda_fp16.h>
#include <cstdint>

// Problem constants
#define BATCH 256
#define TT    256
#define DM    384
#define DKV   64
#define BT    (BATCH*TT)

// ---------------------------------------------------------------------------
// Scratch: only W^T fp16 remains in gmem. q/k/v never leave shared memory.
// ---------------------------------------------------------------------------
__device__ __align__(16) __half g_wh[192 * DM];

// ---------------------------------------------------------------------------
// PTX helpers (sm_80-era: mma.sync + ldmatrix + cp.async, valid at compute_103)
// ---------------------------------------------------------------------------
__device__ __forceinline__ uint32_t smem_u32(const void* p) {
    uint32_t a;
    asm("{ .reg .u64 t; cvta.to.shared.u64 t, %1; cvt.u32.u64 %0, t; }"
        : "=r"(a) : "l"(p));
    return a;
}
__device__ __forceinline__ void ldsm_x4(uint32_t addr, uint32_t* r) {
    asm volatile("ldmatrix.sync.aligned.m8n8.x4.shared.b16 {%0,%1,%2,%3}, [%4];"
                 : "=r"(r[0]), "=r"(r[1]), "=r"(r[2]), "=r"(r[3]) : "r"(addr));
}
__device__ __forceinline__ void ldsm_x4t(uint32_t addr, uint32_t* r) {
    asm volatile("ldmatrix.sync.aligned.m8n8.x4.trans.shared.b16 {%0,%1,%2,%3}, [%4];"
                 : "=r"(r[0]), "=r"(r[1]), "=r"(r[2]), "=r"(r[3]) : "r"(addr));
}
__device__ __forceinline__ void mma_fp16(float* c, const uint32_t* a,
                                         uint32_t b0, uint32_t b1) {
    asm volatile(
        "mma.sync.aligned.m16n8k16.row.col.f32.f16.f16.f32 "
        "{%0,%1,%2,%3}, {%4,%5,%6,%7}, {%8,%9}, {%0,%1,%2,%3};"
        : "+f"(c[0]), "+f"(c[1]), "+f"(c[2]), "+f"(c[3])
        : "r"(a[0]), "r"(a[1]), "r"(a[2]), "r"(a[3]), "r"(b0), "r"(b1));
}
__device__ __forceinline__ float ex2(float x) {
    float y;
    asm("ex2.approx.ftz.f32 %0, %1;" : "=f"(y) : "f"(x));
    return y;
}
__device__ __forceinline__ void split2h(float x, float y, uint32_t& h, uint32_t& l) {
    __half h0 = __float2half_rn(x), h1 = __float2half_rn(y);
    __half l0 = __float2half_rn(x - __half2float(h0));
    __half l1 = __float2half_rn(y - __half2float(h1));
    __half2 hp = __halves2half2(h0, h1);
    __half2 lp = __halves2half2(l0, l1);
    h = *(uint32_t*)&hp; l = *(uint32_t*)&lp;
}
__device__ __forceinline__ uint32_t pack2h(float x, float y) {
    __half2 hp = __halves2half2(__float2half_rn(x), __float2half_rn(y));
    return *(uint32_t*)&hp;
}
#define CP_ASYNC16(dst, src) \
    asm volatile("cp.async.cg.shared.global [%0], [%1], 16;" \
                 :: "r"(dst), "l"(src) : "memory")
#define CP_COMMIT() asm volatile("cp.async.commit_group;" ::: "memory")
#define CP_WAIT(n)  asm volatile("cp.async.wait_group %0;" :: "n"(n) : "memory")

// ---------------------------------------------------------------------------
// Kernel 0: W^T fp16 conversion, coalesced reads via smem transpose.
// ---------------------------------------------------------------------------
__global__ void wconv_kernel(const float* __restrict__ Wq,
                             const float* __restrict__ Wk,
                             const float* __restrict__ Wv) {
    __shared__ float t[32][65];
    const int mat = blockIdx.x / 12;          // 0..2
    const int k0  = (blockIdx.x % 12) * 32;
    const float* W = (mat == 0) ? Wq : (mat == 1) ? Wk : Wv;
    const int tid = threadIdx.x;

    {
        const int n  = tid & 63;
        const int kl = tid >> 6;
        #pragma unroll
        for (int i = 0; i < 8; i++) {
            const int k = kl + i * 4;
            t[k][n] = W[(size_t)(k0 + k) * DKV + n];
        }
    }
    __syncthreads();
    {
        const int kl = tid & 31;
        const int nl = tid >> 5;
        #pragma unroll
        for (int i = 0; i < 8; i++) {
            const int n = nl + i * 8;
            g_wh[(size_t)(mat * 64 + n) * DM + k0 + kl] = __float2half_rn(t[kl][n]);
        }
    }
}

// ---------------------------------------------------------------------------
// FUSED kernel: per-batch QKV projection (2 x proj pipeline, epilogue to smem)
// followed by causal attention. Warp w processes m16 tiles (w, 15-w) JOINTLY
// in one key-round loop: exact 9 MMA-round balance + 2-tile ILP.
// ---------------------------------------------------------------------------
#define BM   128
#define BKS  32
#define NKS  (DM / BKS)
#define PAD  40
#define APAD 72

#define A_SZ (BM * PAD)          // 5120
#define B_SZ (192 * PAD)         // 7680
#define OFF_A(buf)  ((buf) * A_SZ)
#define OFF_B(buf)  (3 * A_SZ + (buf) * B_SZ)
#define OFF_QH      (3 * A_SZ + 3 * B_SZ)          // 38400
#define OFF_QL      (OFF_QH + TT * APAD)
#define OFF_KH      (OFF_QL + TT * APAD)
#define OFF_VH      (OFF_KH + TT * APAD)
#define SM_TOT      (OFF_VH + TT * APAD)           // 112128 fp16 = 224256 B

__global__ void __launch_bounds__(256, 1) fused_kernel(const float* __restrict__ X,
                                                       float* __restrict__ out) {
    extern __shared__ __half sm[];
    const uint32_t sb = smem_u32(sm);

    const int b    = blockIdx.x;
    const int tid  = threadIdx.x;
    const int lane = tid & 31;
    const int wid  = tid >> 5;
    const int warp_m = wid & 3;
    const int warp_n = wid >> 2;

    // =====================  PHASE 1: projection (2 halves)  =================
    for (int hf = 0; hf < 2; hf++) {
        const int row0 = b * TT + hf * BM;

        float acc[2][12][4];
        #pragma unroll
        for (int m = 0; m < 2; m++)
            #pragma unroll
            for (int n = 0; n < 12; n++)
                #pragma unroll
                for (int j = 0; j < 4; j++) acc[m][n][j] = 0.f;

        float4 xa[4];
        const int br  = tid >> 2;
        const int bc8 = tid & 3;

        auto cp_b = [&](int ks, int buf) {
            const int k0 = ks * BKS;
            #pragma unroll
            for (int i = 0; i < 3; i++) {
                int r = br + i * 64;
                uint32_t dst = sb + (uint32_t)(OFF_B(buf) + r * PAD + bc8 * 8) * 2;
                CP_ASYNC16(dst, g_wh + r * DM + k0 + bc8 * 8);
            }
        };
        auto load_x = [&](int ks) {
            const int k0 = ks * BKS;
            #pragma unroll
            for (int i = 0; i < 4; i++) {
                int f  = tid + i * 256;
                int r  = f >> 3;
                int c4 = f & 7;
                xa[i] = *(const float4*)(X + (size_t)(row0 + r) * DM + k0 + c4 * 4);
            }
        };
        auto store_x = [&](int buf) {
            #pragma unroll
            for (int i = 0; i < 4; i++) {
                int f  = tid + i * 256;
                int r  = f >> 3;
                int c4 = f & 7;
                float4 v = xa[i];
                *(uint2*)(sm + OFF_A(buf) + r * PAD + c4 * 4) =
                    make_uint2(pack2h(v.x, v.y), pack2h(v.z, v.w));
            }
        };

        cp_b(0, 0); CP_COMMIT();
        cp_b(1, 1); CP_COMMIT();
        load_x(0);
        store_x(0);
        CP_WAIT(1);
        __syncthreads();

        for (int ks = 0; ks < NKS; ks++) {
            if (ks + 2 < NKS) { cp_b(ks + 2, (ks + 2) % 3); CP_COMMIT(); }
            if (ks + 1 < NKS) load_x(ks + 1);

            const uint32_t a_base = sb + OFF_A(ks % 3) * 2;
            const uint32_t b_base = sb + OFF_B(ks % 3) * 2;

            #pragma unroll
            for (int kk = 0; kk < 2; kk++) {
                uint32_t ah[2][4];
                const int arow_l = (lane & 15);
                const int acol   = kk * 16 + ((lane >> 4) << 3);
                #pragma unroll
                for (int mt = 0; mt < 2; mt++) {
                    const int arow = warp_m * 32 + mt * 16 + arow_l;
                    ldsm_x4(a_base + (uint32_t)(arow * PAD + acol) * 2, ah[mt]);
                }
                const int brow_l = (lane & 7) + ((lane & 16) >> 1);
                const int bcol   = kk * 16 + (lane & 8);
                #pragma unroll
                for (int g2 = 0; g2 < 6; g2++) {
                    uint32_t bh[4];
                    const int brow = warp_n * 96 + g2 * 16 + brow_l;
                    ldsm_x4(b_base + (uint32_t)(brow * PAD + bcol) * 2, bh);
                    #pragma unroll
                    for (int mt = 0; mt < 2; mt++) {
                        #pragma unroll
                        for (int h = 0; h < 2; h++) {
                            mma_fp16(acc[mt][g2 * 2 + h], ah[mt],
                                     bh[h * 2], bh[h * 2 + 1]);
                        }
                    }
                }
            }

            if (ks + 1 < NKS) {
                store_x((ks + 1) % 3);
                if (ks + 2 < NKS) { CP_WAIT(1); }
                else              { CP_WAIT(0); }
                __syncthreads();
            }
        }

        // ---- epilogue: q -> smem hi/lo fp16, k/v -> smem fp16 ----
        const int gi = lane >> 2;
        const int ti = lane & 3;
        #pragma unroll
        for (int mt = 0; mt < 2; mt++) {
            const int lrow = hf * BM + warp_m * 32 + mt * 16 + gi;
            #pragma unroll
            for (int nt = 0; nt < 12; nt++) {
                const int col = warp_n * 96 + nt * 8 + ti * 2;
                if (col < 64) {
                    uint32_t h0, l0, h1, l1;
                    split2h(acc[mt][nt][0], acc[mt][nt][1], h0, l0);
                    split2h(acc[mt][nt][2], acc[mt][nt][3], h1, l1);
                    *(uint32_t*)(sm + OFF_QH + lrow * APAD + col) = h0;
                    *(uint32_t*)(sm + OFF_QL + lrow * APAD + col) = l0;
                    *(uint32_t*)(sm + OFF_QH + (lrow + 8) * APAD + col) = h1;
                    *(uint32_t*)(sm + OFF_QL + (lrow + 8) * APAD + col) = l1;
                } else {
                    const int o = (col < 128) ? OFF_KH : OFF_VH;
                    const int c = col & 63;
                    *(uint32_t*)(sm + o + lrow * APAD + c) =
                        pack2h(acc[mt][nt][0], acc[mt][nt][1]);
                    *(uint32_t*)(sm + o + (lrow + 8) * APAD + c) =
                        pack2h(acc[mt][nt][2], acc[mt][nt][3]);
                }
            }
        }
        __syncthreads();
    }

    // =====================  PHASE 2: causal attention  ======================
    // Warp w: tiles ta=w (shallow) and tb=15-w (deep), joint round loop.
    const int ta  = wid;
    const int tb  = 15 - wid;
    const int nra = (ta + 2) >> 1;        // rounds tile a participates
    const int nrb = (tb + 2) >> 1;        // total loop trips (nrb >= nra)
    const int g  = lane >> 2;
    const int tg = lane & 3;
    const float SC = 0.125f * 1.44269504f;

    // Q fragments (mt=0 -> tile a, mt=1 -> tile b)
    uint32_t qh[2][4][4], ql[2][4][4];
    #pragma unroll
    for (int mt = 0; mt < 2; mt++) {
        const int R0 = (mt ? tb : ta) * 16;
        #pragma unroll
        for (int kk = 0; kk < 4; kk++) {
            const int arow = R0 + (lane & 15);
            const int acol = kk * 16 + ((lane >> 4) << 3);
            ldsm_x4(sb + (uint32_t)(OFF_QH + arow * APAD + acol) * 2, qh[mt][kk]);
            ldsm_x4(sb + (uint32_t)(OFF_QL + arow * APAD + acol) * 2, ql[mt][kk]);
        }
    }

    float m[4] = {-1e30f, -1e30f, -1e30f, -1e30f};
    float lsum[4] = {0.f, 0.f, 0.f, 0.f};
    float O[2][8][4];
    #pragma unroll
    for (int mt = 0; mt < 2; mt++)
        #pragma unroll
        for (int n = 0; n < 8; n++)
            #pragma unroll
            for (int j = 0; j < 4; j++) O[mt][n][j] = 0.f;

    const int krow = (lane & 7) + ((lane & 16) >> 1);
    const int koff = (lane & 8);
    const int vkey = lane & 15;
    const int voff = (lane >> 4) << 3;

    for (int kr = 0; kr < nrb; kr++) {
        const int j0 = kr * 32;
        const bool act_a = (kr < nra);        // warp-uniform
        const bool msk_a = (kr == nra - 1);
        const bool msk_b = (kr == nrb - 1);

        float S[2][4][4];
        #pragma unroll
        for (int mt = 0; mt < 2; mt++)
            #pragma unroll
            for (int nt = 0; nt < 4; nt++)
                #pragma unroll
                for (int j = 0; j < 4; j++) S[mt][nt][j] = 0.f;

        const uint32_t kb0 = sb + (uint32_t)(OFF_KH + (j0 + krow) * APAD + koff) * 2;
        const uint32_t kb1 = kb0 + (uint32_t)(16 * APAD) * 2;
        #pragma unroll
        for (int kk = 0; kk < 4; kk++) {
            uint32_t b0[4], b1[4];
            ldsm_x4(kb0 + kk * 32, b0);
            ldsm_x4(kb1 + kk * 32, b1);
            if (act_a) {
                mma_fp16(S[0][0], qh[0][kk], b0[0], b0[1]);
                mma_fp16(S[0][1], qh[0][kk], b0[2], b0[3]);
                mma_fp16(S[0][2], qh[0][kk], b1[0], b1[1]);
                mma_fp16(S[0][3], qh[0][kk], b1[2], b1[3]);
                mma_fp16(S[0][0], ql[0][kk], b0[0], b0[1]);
                mma_fp16(S[0][1], ql[0][kk], b0[2], b0[3]);
                mma_fp16(S[0][2], ql[0][kk], b1[0], b1[1]);
                mma_fp16(S[0][3], ql[0][kk], b1[2], b1[3]);
            }
            mma_fp16(S[1][0], qh[1][kk], b0[0], b0[1]);
            mma_fp16(S[1][1], qh[1][kk], b0[2], b0[3]);
            mma_fp16(S[1][2], qh[1][kk], b1[0], b1[1]);
            mma_fp16(S[1][3], qh[1][kk], b1[2], b1[3]);
            mma_fp16(S[1][0], ql[1][kk], b0[0], b0[1]);
            mma_fp16(S[1][1], ql[1][kk], b0[2], b0[3]);
            mma_fp16(S[1][2], ql[1][kk], b1[0], b1[1]);
            mma_fp16(S[1][3], ql[1][kk], b1[2], b1[3]);
        }

        // ---- causal masks (per tile, its own last round) ----
        if (msk_a && act_a) {
            #pragma unroll
            for (int nt = 0; nt < 4; nt++)
                #pragma unroll
                for (int j = 0; j < 4; j++) {
                    const int row = ta * 16 + g + ((j >> 1) << 3);
                    const int col = j0 + nt * 8 + tg * 2 + (j & 1);
                    if (col > row) S[0][nt][j] = -3e38f;
                }
        }
        if (msk_b) {
            #pragma unroll
            for (int nt = 0; nt < 4; nt++)
                #pragma unroll
                for (int j = 0; j < 4; j++) {
                    const int row = tb * 16 + g + ((j >> 1) << 3);
                    const int col = j0 + nt * 8 + tg * 2 + (j & 1);
                    if (col > row) S[1][nt][j] = -3e38f;
                }
        }

        // ---- online softmax + P frags ----
        uint32_t pa0[2][4], pa1[2][4];
        #pragma unroll
        for (int mt = 0; mt < 2; mt++) {
            if (mt == 0 && !act_a) continue;
            #pragma unroll
            for (int h = 0; h < 2; h++) {
                const int rg = mt * 2 + h;
                float v0 = S[mt][0][h * 2] * SC, v1 = S[mt][0][h * 2 + 1] * SC;
                float v2 = S[mt][1][h * 2] * SC, v3 = S[mt][1][h * 2 + 1] * SC;
                float v4 = S[mt][2][h * 2] * SC, v5 = S[mt][2][h * 2 + 1] * SC;
                float v6 = S[mt][3][h * 2] * SC, v7 = S[mt][3][h * 2 + 1] * SC;
                float mx = fmaxf(fmaxf(fmaxf(v0, v1), fmaxf(v2, v3)),
                                 fmaxf(fmaxf(v4, v5), fmaxf(v6, v7)));
                mx = fmaxf(mx, __shfl_xor_sync(0xFFFFFFFFu, mx, 1));
                mx = fmaxf(mx, __shfl_xor_sync(0xFFFFFFFFu, mx, 2));
                const float mnew = fmaxf(m[rg], mx);
                const float sc   = ex2(m[rg] - mnew);
                m[rg] = mnew;
                const float p0 = ex2(v0 - mnew), p1 = ex2(v1 - mnew);
                const float p2 = ex2(v2 - mnew), p3 = ex2(v3 - mnew);
                const float p4 = ex2(v4 - mnew), p5 = ex2(v5 - mnew);
                const float p6 = ex2(v6 - mnew), p7 = ex2(v7 - mnew);
                lsum[rg] = lsum[rg] * sc +
                           ((p0 + p1) + (p2 + p3)) + ((p4 + p5) + (p6 + p7));
                #pragma unroll
                for (int n = 0; n < 8; n++) {
                    O[mt][n][h * 2]     *= sc;
                    O[mt][n][h * 2 + 1] *= sc;
                }
                pa0[mt][h]     = pack2h(p0, p1);
                pa0[mt][2 + h] = pack2h(p2, p3);
                pa1[mt][h]     = pack2h(p4, p5);
                pa1[mt][2 + h] = pack2h(p6, p7);
            }
        }

        // ---- O += P V ----
        const uint32_t vb0 = sb + (uint32_t)(OFF_VH + (j0 + vkey) * APAD + voff) * 2;
        const uint32_t vb1 = vb0 + (uint32_t)(16 * APAD) * 2;
        #pragma unroll
        for (int nc = 0; nc < 4; nc++) {
            uint32_t v0[4], v1[4];
            ldsm_x4t(vb0 + nc * 32, v0);
            ldsm_x4t(vb1 + nc * 32, v1);
            if (act_a) {
                mma_fp16(O[0][nc * 2],     pa0[0], v0[0], v0[1]);
                mma_fp16(O[0][nc * 2 + 1], pa0[0], v0[2], v0[3]);
                mma_fp16(O[0][nc * 2],     pa1[0], v1[0], v1[1]);
                mma_fp16(O[0][nc * 2 + 1], pa1[0], v1[2], v1[3]);
            }
            mma_fp16(O[1][nc * 2],     pa0[1], v0[0], v0[1]);
            mma_fp16(O[1][nc * 2 + 1], pa0[1], v0[2], v0[3]);
            mma_fp16(O[1][nc * 2],     pa1[1], v1[0], v1[1]);
            mma_fp16(O[1][nc * 2 + 1], pa1[1], v1[2], v1[3]);
        }
    }

    // ---- epilogue: quad-reduce l, normalize, store ----
    float* ob = out + ((size_t)b * TT) * DKV;
    #pragma unroll
    for (int mt = 0; mt < 2; mt++) {
        const int R0 = (mt ? tb : ta) * 16;
        #pragma unroll
        for (int h = 0; h < 2; h++) {
            float ls = lsum[mt * 2 + h];
            ls += __shfl_xor_sync(0xFFFFFFFFu, ls, 1);
            ls += __shfl_xor_sync(0xFFFFFFFFu, ls, 2);
            const float iv = 1.f / ls;
            const int row = R0 + g + h * 8;
            #pragma unroll
            for (int n = 0; n < 8; n++) {
                *(float2*)(ob + (size_t)row * DKV + n * 8 + tg * 2) =
                    make_float2(O[mt][n][h * 2] * iv, O[mt][n][h * 2 + 1] * iv);
            }
        }
    }
}

// ---------------------------------------------------------------------------
// kernel_launch — graph-capturable, allocation-free
// ---------------------------------------------------------------------------
extern "C" void kernel_launch(void* const* d_in, const int* in_sizes, int n_in,
                              void* d_out, int out_size) {
    const float* x  = (const float*)d_in[0];
    const float* Wq = (const float*)d_in[1];
    const float* Wk = (const float*)d_in[2];
    const float* Wv = (const float*)d_in[3];
    float* out = (float*)d_out;
    (void)in_sizes; (void)n_in; (void)out_size;

    wconv_kernel<<<36, 256>>>(Wq, Wk, Wv);

    const int fused_smem = SM_TOT * (int)sizeof(__half);   // 224256 B
    cudaFuncSetAttribute(fused_kernel,
                         cudaFuncAttributeMaxDynamicSharedMemorySize, fused_smem);
    fused_kernel<<<BATCH, 256, fused_smem>>>(x, out);
}